// round 2
// baseline (speedup 1.0000x reference)
#include <cuda_runtime.h>

// x [B=4096, T=512, D=4], H=32, 2 stacked LSTM layers, gate rows i,f,g,o (0..127),
// head: out[b] = h2[T-1] . W_out + b_out.
#define TT 512
#define DD 4

typedef unsigned long long ull;

// ---- packed f32x2 helpers (sm_103a FFMA2 path, PTX-only) ----
__device__ __forceinline__ ull ffma2(ull a, ull b, ull c) {
    ull d;
    asm("fma.rn.f32x2 %0, %1, %2, %3;" : "=l"(d) : "l"(a), "l"(b), "l"(c));
    return d;
}
__device__ __forceinline__ ull fadd2(ull a, ull b) {
    ull d;
    asm("add.rn.f32x2 %0, %1, %2;" : "=l"(d) : "l"(a), "l"(b));
    return d;
}
__device__ __forceinline__ ull fpack(float lo, float hi) {
    ull d;
    asm("mov.b64 %0, {%1, %2};" : "=l"(d) : "f"(lo), "f"(hi));
    return d;
}
__device__ __forceinline__ float funpack_sum(ull p) {   // lo + hi
    float lo, hi;
    asm("mov.b64 {%0, %1}, %2;" : "=f"(lo), "=f"(hi) : "l"(p));
    return lo + hi;
}

__device__ __forceinline__ float fsig(float x) {
    return __fdividef(1.0f, 1.0f + __expf(-x));   // MUFU EX2 + RCP, ~1e-6 abs err
}
__device__ __forceinline__ float ftanh(float x) {
    return 1.0f - __fdividef(2.0f, __expf(2.0f * x) + 1.0f);
}

__global__ __launch_bounds__(128, 4)
void lstm2_kernel(const float* __restrict__ x,
                  const float* __restrict__ Wih0, const float* __restrict__ Whh0,
                  const float* __restrict__ bih0, const float* __restrict__ bhh0,
                  const float* __restrict__ Wih1, const float* __restrict__ Whh1,
                  const float* __restrict__ bih1, const float* __restrict__ bhh1,
                  const float* __restrict__ Wout, const float* __restrict__ bout,
                  float* __restrict__ out)
{
    const int b    = blockIdx.x;
    const int tid  = threadIdx.x;   // gate-row index: warps = i,f,g,o
    const int gate = tid >> 5;      // activation choice is warp-uniform
    const int lane = tid & 31;      // hidden unit

    __shared__ __align__(16) float h0s[32];
    __shared__ __align__(16) float h1s[32];
    __shared__ float ga0[128];
    __shared__ float ga1[128];

    // ---- weights into register PAIRS (j-dimension packed 2-wide) ----
    ull wih0p[2], whh0p[16], wih1p[16], whh1p[16];
    {
        const ulonglong2* r;
        r = reinterpret_cast<const ulonglong2*>(Wih0 + tid * 4);
        { ulonglong2 v = r[0]; wih0p[0] = v.x; wih0p[1] = v.y; }
        r = reinterpret_cast<const ulonglong2*>(Whh0 + tid * 32);
        #pragma unroll
        for (int k = 0; k < 8; ++k) { ulonglong2 v = r[k]; whh0p[2*k] = v.x; whh0p[2*k+1] = v.y; }
        r = reinterpret_cast<const ulonglong2*>(Wih1 + tid * 32);
        #pragma unroll
        for (int k = 0; k < 8; ++k) { ulonglong2 v = r[k]; wih1p[2*k] = v.x; wih1p[2*k+1] = v.y; }
        r = reinterpret_cast<const ulonglong2*>(Whh1 + tid * 32);
        #pragma unroll
        for (int k = 0; k < 8; ++k) { ulonglong2 v = r[k]; whh1p[2*k] = v.x; whh1p[2*k+1] = v.y; }
    }
    const ull bias0p = fpack(bih0[tid] + bhh0[tid], 0.0f);
    const ull bias1p = fpack(bih1[tid] + bhh1[tid], 0.0f);
    const ull ZP = 0ull;

    if (tid < 32) { h0s[tid] = 0.0f; h1s[tid] = 0.0f; }
    __syncthreads();

    float c0 = 0.0f, c1 = 0.0f;
    const ulonglong2* Xp = reinterpret_cast<const ulonglong2*>(x + (size_t)b * (TT * DD));
    ulonglong2 xv = Xp[0];                       // x[b,0,:] as two f32x2 pairs

    const ulonglong2* H0p = reinterpret_cast<const ulonglong2*>(h0s);
    const ulonglong2* H1p = reinterpret_cast<const ulonglong2*>(h1s);

    for (int t = 0; t < TT; ++t) {
        // -------- layer 0: bias + x.Wih0 + h0.Whh0 (packed 2-wide) --------
        ull a0 = ffma2(xv.x, wih0p[0], bias0p);
        ull a1 = ffma2(xv.y, wih0p[1], ZP);
        #pragma unroll
        for (int k = 0; k < 8; ++k) {
            ulonglong2 h = H0p[k];               // broadcast LDS.128 -> 2 pairs
            a0 = ffma2(h.x, whh0p[2*k],   a0);
            a1 = ffma2(h.y, whh0p[2*k+1], a1);
        }
        float pre0 = funpack_sum(fadd2(a0, a1));

        if (t + 1 < TT) xv = Xp[t + 1];          // prefetch next x

        ga0[tid] = (gate == 2) ? ftanh(pre0) : fsig(pre0);
        __syncthreads();                         // gate exchange, layer 0

        {   // redundant (value-identical) c/h update in every warp: no 2nd barrier
            float gi = ga0[lane], gf = ga0[32 + lane], gg = ga0[64 + lane], go = ga0[96 + lane];
            c0 = fmaf(gf, c0, gi * gg);
            h0s[lane] = go * ftanh(c0);
        }
        __syncwarp();

        // -------- layer 1: bias + h0.Wih1 + h1.Whh1 (packed 2-wide) --------
        ull u0 = bias1p, u1 = ZP, u2 = ZP, u3 = ZP;
        #pragma unroll
        for (int k = 0; k < 8; ++k) {
            ulonglong2 a = H0p[k];
            ulonglong2 h = H1p[k];
            u0 = ffma2(a.x, wih1p[2*k],   u0);
            u1 = ffma2(a.y, wih1p[2*k+1], u1);
            u2 = ffma2(h.x, whh1p[2*k],   u2);
            u3 = ffma2(h.y, whh1p[2*k+1], u3);
        }
        float pre1 = funpack_sum(fadd2(fadd2(u0, u1), fadd2(u2, u3)));

        ga1[tid] = (gate == 2) ? ftanh(pre1) : fsig(pre1);
        __syncthreads();                         // gate exchange, layer 1

        {
            float gi = ga1[lane], gf = ga1[32 + lane], gg = ga1[64 + lane], go = ga1[96 + lane];
            c1 = fmaf(gf, c1, gi * gg);
            h1s[lane] = go * ftanh(c1);
        }
        __syncwarp();
    }

    // -------- head: out[b] = h1 . Wout + bout --------
    if (tid < 32) {
        float v = h1s[lane] * Wout[lane];
        #pragma unroll
        for (int o = 16; o > 0; o >>= 1)
            v += __shfl_down_sync(0xffffffffu, v, o);
        if (lane == 0) out[b] = v + bout[0];
    }
}

extern "C" void kernel_launch(void* const* d_in, const int* in_sizes, int n_in,
                              void* d_out, int out_size)
{
    const float* x    = (const float*)d_in[0];
    const float* Wih0 = (const float*)d_in[1];
    const float* Whh0 = (const float*)d_in[2];
    const float* bih0 = (const float*)d_in[3];
    const float* bhh0 = (const float*)d_in[4];
    const float* Wih1 = (const float*)d_in[5];
    const float* Whh1 = (const float*)d_in[6];
    const float* bih1 = (const float*)d_in[7];
    const float* bhh1 = (const float*)d_in[8];
    const float* Wout = (const float*)d_in[9];
    const float* bout = (const float*)d_in[10];

    const int B = out_size;   // 4096
    lstm2_kernel<<<B, 128>>>(x, Wih0, Whh0, bih0, bhh0,
                             Wih1, Whh1, bih1, bhh1,
                             Wout, bout, (float*)d_out);
}

// round 3
// speedup vs baseline: 1.0797x; 1.0797x over previous
#include <cuda_runtime.h>

// x [B=4096, T=512, D=4], H=32, 2 stacked LSTM layers, gate rows i,f,g,o (0..127),
// head: out[b] = h2[T-1] . W_out + b_out.
#define TT 512
#define DD 4

__device__ __forceinline__ float fsig(float x) {
    return __fdividef(1.0f, 1.0f + __expf(-x));   // MUFU EX2 + RCP, ~1e-6 abs err
}
__device__ __forceinline__ float ftanh(float x) {
    return 1.0f - __fdividef(2.0f, __expf(2.0f * x) + 1.0f);
}

__global__ __launch_bounds__(128, 4)
void lstm2_kernel(const float* __restrict__ x,
                  const float* __restrict__ Wih0, const float* __restrict__ Whh0,
                  const float* __restrict__ bih0, const float* __restrict__ bhh0,
                  const float* __restrict__ Wih1, const float* __restrict__ Whh1,
                  const float* __restrict__ bih1, const float* __restrict__ bhh1,
                  const float* __restrict__ Wout, const float* __restrict__ bout,
                  float* __restrict__ out)
{
    const int b    = blockIdx.x;
    const int tid  = threadIdx.x;   // gate-row index: warps = i,f,g,o
    const int gate = tid >> 5;      // activation choice is warp-uniform
    const int lane = tid & 31;      // hidden unit

    __shared__ __align__(16) float h0s[32];   // h of layer 0 (current step in flight)
    __shared__ __align__(16) float h1s[32];   // h of layer 1
    __shared__ float ga0[128];                // layer-0 gate activations (for step t+1)
    __shared__ float ga1[128];                // layer-1 gate activations (for step t)

    // ---- weights resident in registers for the whole recurrence ----
    float wih0[4], whh0[32], wih1[32], whh1[32];
    {
        float4 w = *reinterpret_cast<const float4*>(Wih0 + tid * 4);
        wih0[0] = w.x; wih0[1] = w.y; wih0[2] = w.z; wih0[3] = w.w;
        const float4* r0 = reinterpret_cast<const float4*>(Whh0 + tid * 32);
        const float4* r1 = reinterpret_cast<const float4*>(Wih1 + tid * 32);
        const float4* r2 = reinterpret_cast<const float4*>(Whh1 + tid * 32);
        #pragma unroll
        for (int k = 0; k < 8; ++k) {
            float4 a = r0[k];
            whh0[4*k+0] = a.x; whh0[4*k+1] = a.y; whh0[4*k+2] = a.z; whh0[4*k+3] = a.w;
            float4 c = r1[k];
            wih1[4*k+0] = c.x; wih1[4*k+1] = c.y; wih1[4*k+2] = c.z; wih1[4*k+3] = c.w;
            float4 d = r2[k];
            whh1[4*k+0] = d.x; whh1[4*k+1] = d.y; whh1[4*k+2] = d.z; whh1[4*k+3] = d.w;
        }
    }
    const float bias0 = bih0[tid] + bhh0[tid];
    const float bias1 = bih1[tid] + bhh1[tid];

    if (tid < 32) { h0s[tid] = 0.0f; h1s[tid] = 0.0f; }
    __syncthreads();

    float c0 = 0.0f, c1 = 0.0f;
    const float4* Xp = reinterpret_cast<const float4*>(x + (size_t)b * (TT * DD));
    const float4* H0 = reinterpret_cast<const float4*>(h0s);
    const float4* H1 = reinterpret_cast<const float4*>(h1s);

    // ================= prologue: layer-0 gates for step 0 (h0 == 0) =================
    {
        float4 x0 = Xp[0];
        float p = fmaf(x0.x, wih0[0], bias0);
        p = fmaf(x0.y, wih0[1], p);
        p = fmaf(x0.z, wih0[2], p);
        p = fmaf(x0.w, wih0[3], p);
        ga0[tid] = (gate == 2) ? ftanh(p) : fsig(p);
    }
    __syncthreads();
    {   // redundant value-identical update in every warp
        float gi = ga0[lane], gf = ga0[32 + lane], gg = ga0[64 + lane], go = ga0[96 + lane];
        c0 = fmaf(gf, c0, gi * gg);
        h0s[lane] = go * ftanh(c0);
    }
    __syncwarp();

    float4 xv = Xp[1];   // x for step 1 (consumed by L0(t+1) in iteration t=0)

    // ===== main loop: ONE barrier per step; L1(t) and L0(t+1) computed together =====
    for (int t = 0; t < TT - 1; ++t) {
        float4 xnext = Xp[(t + 2 < TT) ? (t + 2) : (TT - 1)];   // prefetch

        // L0(t+1): bias0 + x(t+1)·wih0 + h0(t)·whh0
        float s0 = fmaf(xv.x, wih0[0], bias0);
        float s1 = xv.y * wih0[1];
        float s2 = xv.z * wih0[2];
        float s3 = xv.w * wih0[3];
        // L1(t): bias1 + h0(t)·wih1 + h1(t-1)·whh1
        float u0 = bias1, u1 = 0.0f, u2 = 0.0f, u3 = 0.0f;
        #pragma unroll
        for (int k = 0; k < 8; ++k) {
            float4 a = H0[k];                 // h0(t), shared by three dots
            float4 h = H1[k];                 // h1(t-1)
            u0 = fmaf(a.x, wih1[4*k+0], u0);
            u1 = fmaf(a.y, wih1[4*k+1], u1);
            u2 = fmaf(a.z, wih1[4*k+2], u2);
            u3 = fmaf(a.w, wih1[4*k+3], u3);
            u0 = fmaf(h.x, whh1[4*k+0], u0);
            u1 = fmaf(h.y, whh1[4*k+1], u1);
            u2 = fmaf(h.z, whh1[4*k+2], u2);
            u3 = fmaf(h.w, whh1[4*k+3], u3);
            s0 = fmaf(a.x, whh0[4*k+0], s0);
            s1 = fmaf(a.y, whh0[4*k+1], s1);
            s2 = fmaf(a.z, whh0[4*k+2], s2);
            s3 = fmaf(a.w, whh0[4*k+3], s3);
        }
        float pre1 = (u0 + u1) + (u2 + u3);
        float pre0 = (s0 + s1) + (s2 + s3);

        ga1[tid] = (gate == 2) ? ftanh(pre1) : fsig(pre1);
        ga0[tid] = (gate == 2) ? ftanh(pre0) : fsig(pre0);
        __syncthreads();                      // the ONLY barrier per step

        {   // update layer 1, step t
            float gi = ga1[lane], gf = ga1[32 + lane], gg = ga1[64 + lane], go = ga1[96 + lane];
            c1 = fmaf(gf, c1, gi * gg);
            h1s[lane] = go * ftanh(c1);
        }
        {   // update layer 0, step t+1
            float gi = ga0[lane], gf = ga0[32 + lane], gg = ga0[64 + lane], go = ga0[96 + lane];
            c0 = fmaf(gf, c0, gi * gg);
            h0s[lane] = go * ftanh(c0);
        }
        __syncwarp();

        xv = xnext;
    }

    // ================= epilogue: L1(TT-1) =================
    {
        float u0 = bias1, u1 = 0.0f, u2 = 0.0f, u3 = 0.0f;
        #pragma unroll
        for (int k = 0; k < 8; ++k) {
            float4 a = H0[k];
            float4 h = H1[k];
            u0 = fmaf(a.x, wih1[4*k+0], u0);
            u1 = fmaf(a.y, wih1[4*k+1], u1);
            u2 = fmaf(a.z, wih1[4*k+2], u2);
            u3 = fmaf(a.w, wih1[4*k+3], u3);
            u0 = fmaf(h.x, whh1[4*k+0], u0);
            u1 = fmaf(h.y, whh1[4*k+1], u1);
            u2 = fmaf(h.z, whh1[4*k+2], u2);
            u3 = fmaf(h.w, whh1[4*k+3], u3);
        }
        float pre1 = (u0 + u1) + (u2 + u3);
        ga1[tid] = (gate == 2) ? ftanh(pre1) : fsig(pre1);
    }
    __syncthreads();

    // -------- head: out[b] = h1(TT-1) . Wout + bout (warp 0 only) --------
    if (tid < 32) {
        float gi = ga1[lane], gf = ga1[32 + lane], gg = ga1[64 + lane], go = ga1[96 + lane];
        c1 = fmaf(gf, c1, gi * gg);
        float h1f = go * ftanh(c1);
        float v = h1f * Wout[lane];
        #pragma unroll
        for (int o = 16; o > 0; o >>= 1)
            v += __shfl_down_sync(0xffffffffu, v, o);
        if (lane == 0) out[b] = v + bout[0];
    }
}

extern "C" void kernel_launch(void* const* d_in, const int* in_sizes, int n_in,
                              void* d_out, int out_size)
{
    const float* x    = (const float*)d_in[0];
    const float* Wih0 = (const float*)d_in[1];
    const float* Whh0 = (const float*)d_in[2];
    const float* bih0 = (const float*)d_in[3];
    const float* bhh0 = (const float*)d_in[4];
    const float* Wih1 = (const float*)d_in[5];
    const float* Whh1 = (const float*)d_in[6];
    const float* bih1 = (const float*)d_in[7];
    const float* bhh1 = (const float*)d_in[8];
    const float* Wout = (const float*)d_in[9];
    const float* bout = (const float*)d_in[10];

    const int B = out_size;   // 4096
    lstm2_kernel<<<B, 128>>>(x, Wih0, Whh0, bih0, bhh0,
                             Wih1, Whh1, bih1, bhh1,
                             Wout, bout, (float*)d_out);
}

// round 4
// speedup vs baseline: 1.1786x; 1.0916x over previous
#include <cuda_runtime.h>

// x [B=4096, T=512, D=4], H=32, 2 stacked LSTM layers, gate rows i,f,g,o (0..127),
// head: out[b] = h2[T-1] . W_out + b_out.
// This version: ONE block = TWO batches (A,B); each thread runs both batches'
// gate-row computation against shared weight registers (ILP-2 latency hiding).
#define TT 512
#define DD 4

__device__ __forceinline__ float fsig(float x) {
    return __fdividef(1.0f, 1.0f + __expf(-x));   // MUFU EX2 + RCP, ~1e-6 abs err
}
__device__ __forceinline__ float ftanh(float x) {
    return 1.0f - __fdividef(2.0f, __expf(2.0f * x) + 1.0f);
}

__global__ __launch_bounds__(128, 3)
void lstm2_kernel(const float* __restrict__ x,
                  const float* __restrict__ Wih0, const float* __restrict__ Whh0,
                  const float* __restrict__ bih0, const float* __restrict__ bhh0,
                  const float* __restrict__ Wih1, const float* __restrict__ Whh1,
                  const float* __restrict__ bih1, const float* __restrict__ bhh1,
                  const float* __restrict__ Wout, const float* __restrict__ bout,
                  float* __restrict__ out)
{
    const int bA   = blockIdx.x * 2;       // batch A
    const int bB   = bA + 1;               // batch B
    const int tid  = threadIdx.x;          // gate-row index: warps = i,f,g,o
    const int gate = tid >> 5;             // activation choice is warp-uniform
    const int lane = tid & 31;             // hidden unit

    __shared__ __align__(16) float h0A[32], h1A[32], h0B[32], h1B[32];
    __shared__ float gA0[128], gA1[128], gB0[128], gB1[128];

    // ---- weights resident in registers, shared by both batch streams ----
    float wih0[4], whh0[32], wih1[32], whh1[32];
    {
        float4 w = *reinterpret_cast<const float4*>(Wih0 + tid * 4);
        wih0[0] = w.x; wih0[1] = w.y; wih0[2] = w.z; wih0[3] = w.w;
        const float4* r0 = reinterpret_cast<const float4*>(Whh0 + tid * 32);
        const float4* r1 = reinterpret_cast<const float4*>(Wih1 + tid * 32);
        const float4* r2 = reinterpret_cast<const float4*>(Whh1 + tid * 32);
        #pragma unroll
        for (int k = 0; k < 8; ++k) {
            float4 a = r0[k];
            whh0[4*k+0] = a.x; whh0[4*k+1] = a.y; whh0[4*k+2] = a.z; whh0[4*k+3] = a.w;
            float4 c = r1[k];
            wih1[4*k+0] = c.x; wih1[4*k+1] = c.y; wih1[4*k+2] = c.z; wih1[4*k+3] = c.w;
            float4 d = r2[k];
            whh1[4*k+0] = d.x; whh1[4*k+1] = d.y; whh1[4*k+2] = d.z; whh1[4*k+3] = d.w;
        }
    }
    const float bias0 = bih0[tid] + bhh0[tid];
    const float bias1 = bih1[tid] + bhh1[tid];

    if (tid < 32) { h0A[tid] = 0.0f; h1A[tid] = 0.0f; h0B[tid] = 0.0f; h1B[tid] = 0.0f; }
    __syncthreads();

    float cA0 = 0.0f, cA1 = 0.0f, cB0 = 0.0f, cB1 = 0.0f;
    const float4* XA = reinterpret_cast<const float4*>(x + (size_t)bA * (TT * DD));
    const float4* XB = reinterpret_cast<const float4*>(x + (size_t)bB * (TT * DD));
    const float4* H0Ap = reinterpret_cast<const float4*>(h0A);
    const float4* H1Ap = reinterpret_cast<const float4*>(h1A);
    const float4* H0Bp = reinterpret_cast<const float4*>(h0B);
    const float4* H1Bp = reinterpret_cast<const float4*>(h1B);

    // ================= prologue: layer-0 gates for step 0 (h0 == 0) =================
    {
        float4 xa = XA[0], xb = XB[0];
        float pA = fmaf(xa.x, wih0[0], bias0);
        pA = fmaf(xa.y, wih0[1], pA);
        pA = fmaf(xa.z, wih0[2], pA);
        pA = fmaf(xa.w, wih0[3], pA);
        float pB = fmaf(xb.x, wih0[0], bias0);
        pB = fmaf(xb.y, wih0[1], pB);
        pB = fmaf(xb.z, wih0[2], pB);
        pB = fmaf(xb.w, wih0[3], pB);
        gA0[tid] = (gate == 2) ? ftanh(pA) : fsig(pA);
        gB0[tid] = (gate == 2) ? ftanh(pB) : fsig(pB);
    }
    __syncthreads();
    {   // redundant value-identical update in every warp (no 2nd barrier needed)
        float gi = gA0[lane], gf = gA0[32 + lane], gg = gA0[64 + lane], go = gA0[96 + lane];
        cA0 = fmaf(gf, cA0, gi * gg);
        h0A[lane] = go * ftanh(cA0);
        gi = gB0[lane]; gf = gB0[32 + lane]; gg = gB0[64 + lane]; go = gB0[96 + lane];
        cB0 = fmaf(gf, cB0, gi * gg);
        h0B[lane] = go * ftanh(cB0);
    }
    __syncwarp();

    float4 xvA = XA[1], xvB = XB[1];   // x for step 1

    // ===== main loop: ONE barrier per step; L1(t) and L0(t+1), both batches =====
    for (int t = 0; t < TT - 1; ++t) {
        const int tn = (t + 2 < TT) ? (t + 2) : (TT - 1);
        float4 xnA = XA[tn], xnB = XB[tn];      // prefetch

        // L0(t+1) accumulators (batch A / B)
        float sA0 = fmaf(xvA.x, wih0[0], bias0);
        float sA1 = xvA.y * wih0[1];
        float sA2 = xvA.z * wih0[2];
        float sA3 = xvA.w * wih0[3];
        float sB0 = fmaf(xvB.x, wih0[0], bias0);
        float sB1 = xvB.y * wih0[1];
        float sB2 = xvB.z * wih0[2];
        float sB3 = xvB.w * wih0[3];
        // L1(t) accumulators
        float uA0 = bias1, uA1 = 0.0f, uA2 = 0.0f, uA3 = 0.0f;
        float uB0 = bias1, uB1 = 0.0f, uB2 = 0.0f, uB3 = 0.0f;
        #pragma unroll
        for (int k = 0; k < 8; ++k) {
            float4 aA = H0Ap[k];                 // h0A(t): feeds 3 dots
            float4 hA = H1Ap[k];                 // h1A(t-1)
            float4 aB = H0Bp[k];
            float4 hB = H1Bp[k];
            uA0 = fmaf(aA.x, wih1[4*k+0], uA0);
            uA1 = fmaf(aA.y, wih1[4*k+1], uA1);
            uA2 = fmaf(aA.z, wih1[4*k+2], uA2);
            uA3 = fmaf(aA.w, wih1[4*k+3], uA3);
            uB0 = fmaf(aB.x, wih1[4*k+0], uB0);
            uB1 = fmaf(aB.y, wih1[4*k+1], uB1);
            uB2 = fmaf(aB.z, wih1[4*k+2], uB2);
            uB3 = fmaf(aB.w, wih1[4*k+3], uB3);
            uA0 = fmaf(hA.x, whh1[4*k+0], uA0);
            uA1 = fmaf(hA.y, whh1[4*k+1], uA1);
            uA2 = fmaf(hA.z, whh1[4*k+2], uA2);
            uA3 = fmaf(hA.w, whh1[4*k+3], uA3);
            uB0 = fmaf(hB.x, whh1[4*k+0], uB0);
            uB1 = fmaf(hB.y, whh1[4*k+1], uB1);
            uB2 = fmaf(hB.z, whh1[4*k+2], uB2);
            uB3 = fmaf(hB.w, whh1[4*k+3], uB3);
            sA0 = fmaf(aA.x, whh0[4*k+0], sA0);
            sA1 = fmaf(aA.y, whh0[4*k+1], sA1);
            sA2 = fmaf(aA.z, whh0[4*k+2], sA2);
            sA3 = fmaf(aA.w, whh0[4*k+3], sA3);
            sB0 = fmaf(aB.x, whh0[4*k+0], sB0);
            sB1 = fmaf(aB.y, whh0[4*k+1], sB1);
            sB2 = fmaf(aB.z, whh0[4*k+2], sB2);
            sB3 = fmaf(aB.w, whh0[4*k+3], sB3);
        }
        float preA1 = (uA0 + uA1) + (uA2 + uA3);
        float preB1 = (uB0 + uB1) + (uB2 + uB3);
        float preA0 = (sA0 + sA1) + (sA2 + sA3);
        float preB0 = (sB0 + sB1) + (sB2 + sB3);

        if (gate == 2) {
            gA1[tid] = ftanh(preA1);
            gB1[tid] = ftanh(preB1);
            gA0[tid] = ftanh(preA0);
            gB0[tid] = ftanh(preB0);
        } else {
            gA1[tid] = fsig(preA1);
            gB1[tid] = fsig(preB1);
            gA0[tid] = fsig(preA0);
            gB0[tid] = fsig(preB0);
        }
        __syncthreads();                      // the ONLY barrier per step

        {   // layer-1 update (step t), batches A and B
            float gi = gA1[lane], gf = gA1[32 + lane], gg = gA1[64 + lane], go = gA1[96 + lane];
            cA1 = fmaf(gf, cA1, gi * gg);
            h1A[lane] = go * ftanh(cA1);
            gi = gB1[lane]; gf = gB1[32 + lane]; gg = gB1[64 + lane]; go = gB1[96 + lane];
            cB1 = fmaf(gf, cB1, gi * gg);
            h1B[lane] = go * ftanh(cB1);
        }
        {   // layer-0 update (step t+1), batches A and B
            float gi = gA0[lane], gf = gA0[32 + lane], gg = gA0[64 + lane], go = gA0[96 + lane];
            cA0 = fmaf(gf, cA0, gi * gg);
            h0A[lane] = go * ftanh(cA0);
            gi = gB0[lane]; gf = gB0[32 + lane]; gg = gB0[64 + lane]; go = gB0[96 + lane];
            cB0 = fmaf(gf, cB0, gi * gg);
            h0B[lane] = go * ftanh(cB0);
        }
        __syncwarp();

        xvA = xnA; xvB = xnB;
    }

    // ================= epilogue: L1(TT-1), both batches =================
    {
        float uA0 = bias1, uA1 = 0.0f, uA2 = 0.0f, uA3 = 0.0f;
        float uB0 = bias1, uB1 = 0.0f, uB2 = 0.0f, uB3 = 0.0f;
        #pragma unroll
        for (int k = 0; k < 8; ++k) {
            float4 aA = H0Ap[k];
            float4 hA = H1Ap[k];
            float4 aB = H0Bp[k];
            float4 hB = H1Bp[k];
            uA0 = fmaf(aA.x, wih1[4*k+0], uA0);
            uA1 = fmaf(aA.y, wih1[4*k+1], uA1);
            uA2 = fmaf(aA.z, wih1[4*k+2], uA2);
            uA3 = fmaf(aA.w, wih1[4*k+3], uA3);
            uB0 = fmaf(aB.x, wih1[4*k+0], uB0);
            uB1 = fmaf(aB.y, wih1[4*k+1], uB1);
            uB2 = fmaf(aB.z, wih1[4*k+2], uB2);
            uB3 = fmaf(aB.w, wih1[4*k+3], uB3);
            uA0 = fmaf(hA.x, whh1[4*k+0], uA0);
            uA1 = fmaf(hA.y, whh1[4*k+1], uA1);
            uA2 = fmaf(hA.z, whh1[4*k+2], uA2);
            uA3 = fmaf(hA.w, whh1[4*k+3], uA3);
            uB0 = fmaf(hB.x, whh1[4*k+0], uB0);
            uB1 = fmaf(hB.y, whh1[4*k+1], uB1);
            uB2 = fmaf(hB.z, whh1[4*k+2], uB2);
            uB3 = fmaf(hB.w, whh1[4*k+3], uB3);
        }
        float preA1 = (uA0 + uA1) + (uA2 + uA3);
        float preB1 = (uB0 + uB1) + (uB2 + uB3);
        gA1[tid] = (gate == 2) ? ftanh(preA1) : fsig(preA1);
        gB1[tid] = (gate == 2) ? ftanh(preB1) : fsig(preB1);
    }
    __syncthreads();

    // -------- heads (warp 0 computes both batches; it holds cA1/cB1 per lane) -----
    if (tid < 32) {
        float gi = gA1[lane], gf = gA1[32 + lane], gg = gA1[64 + lane], go = gA1[96 + lane];
        cA1 = fmaf(gf, cA1, gi * gg);
        float hAf = go * ftanh(cA1);
        gi = gB1[lane]; gf = gB1[32 + lane]; gg = gB1[64 + lane]; go = gB1[96 + lane];
        cB1 = fmaf(gf, cB1, gi * gg);
        float hBf = go * ftanh(cB1);

        float w = Wout[lane];
        float vA = hAf * w;
        float vB = hBf * w;
        #pragma unroll
        for (int o = 16; o > 0; o >>= 1) {
            vA += __shfl_down_sync(0xffffffffu, vA, o);
            vB += __shfl_down_sync(0xffffffffu, vB, o);
        }
        if (lane == 0) {
            float bo = bout[0];
            out[bA] = vA + bo;
            out[bB] = vB + bo;
        }
    }
}

extern "C" void kernel_launch(void* const* d_in, const int* in_sizes, int n_in,
                              void* d_out, int out_size)
{
    const float* x    = (const float*)d_in[0];
    const float* Wih0 = (const float*)d_in[1];
    const float* Whh0 = (const float*)d_in[2];
    const float* bih0 = (const float*)d_in[3];
    const float* bhh0 = (const float*)d_in[4];
    const float* Wih1 = (const float*)d_in[5];
    const float* Whh1 = (const float*)d_in[6];
    const float* bih1 = (const float*)d_in[7];
    const float* bhh1 = (const float*)d_in[8];
    const float* Wout = (const float*)d_in[9];
    const float* bout = (const float*)d_in[10];

    const int B = out_size;     // 4096
    lstm2_kernel<<<B / 2, 128>>>(x, Wih0, Whh0, bih0, bhh0,
                                 Wih1, Whh1, bih1, bhh1,
                                 Wout, bout, (float*)d_out);
}

// round 5
// speedup vs baseline: 1.4818x; 1.2573x over previous
#include <cuda_runtime.h>

// x [B=4096, T=512, D=4], H=32, 2 stacked LSTM layers, gate rows i,f,g,o (0..127),
// head: out[b] = h2[T-1] . W_out + b_out.
// ONE block = TWO batches (A,B); shared weight registers; single barrier/step.
// This round: all activations via hardware MUFU.TANH (tanh.approx.f32).
#define TT 512
#define DD 4

__device__ __forceinline__ float tanh_hw(float x) {
    float y;
    asm("tanh.approx.f32 %0, %1;" : "=f"(y) : "f"(x));
    return y;
}
__device__ __forceinline__ float fsig(float x) {
    // sigmoid(x) = 0.5*tanh(0.5x) + 0.5   (1 MUFU + 2 fma-pipe ops)
    return fmaf(0.5f, tanh_hw(0.5f * x), 0.5f);
}
__device__ __forceinline__ float ftanh(float x) { return tanh_hw(x); }

__global__ __launch_bounds__(128, 3)
void lstm2_kernel(const float* __restrict__ x,
                  const float* __restrict__ Wih0, const float* __restrict__ Whh0,
                  const float* __restrict__ bih0, const float* __restrict__ bhh0,
                  const float* __restrict__ Wih1, const float* __restrict__ Whh1,
                  const float* __restrict__ bih1, const float* __restrict__ bhh1,
                  const float* __restrict__ Wout, const float* __restrict__ bout,
                  float* __restrict__ out)
{
    const int bA   = blockIdx.x * 2;       // batch A
    const int bB   = bA + 1;               // batch B
    const int tid  = threadIdx.x;          // gate-row index: warps = i,f,g,o
    const int gate = tid >> 5;             // activation choice is warp-uniform
    const int lane = tid & 31;             // hidden unit

    __shared__ __align__(16) float h0A[32], h1A[32], h0B[32], h1B[32];
    __shared__ float gA0[128], gA1[128], gB0[128], gB1[128];

    // ---- weights resident in registers, shared by both batch streams ----
    float wih0[4], whh0[32], wih1[32], whh1[32];
    {
        float4 w = *reinterpret_cast<const float4*>(Wih0 + tid * 4);
        wih0[0] = w.x; wih0[1] = w.y; wih0[2] = w.z; wih0[3] = w.w;
        const float4* r0 = reinterpret_cast<const float4*>(Whh0 + tid * 32);
        const float4* r1 = reinterpret_cast<const float4*>(Wih1 + tid * 32);
        const float4* r2 = reinterpret_cast<const float4*>(Whh1 + tid * 32);
        #pragma unroll
        for (int k = 0; k < 8; ++k) {
            float4 a = r0[k];
            whh0[4*k+0] = a.x; whh0[4*k+1] = a.y; whh0[4*k+2] = a.z; whh0[4*k+3] = a.w;
            float4 c = r1[k];
            wih1[4*k+0] = c.x; wih1[4*k+1] = c.y; wih1[4*k+2] = c.z; wih1[4*k+3] = c.w;
            float4 d = r2[k];
            whh1[4*k+0] = d.x; whh1[4*k+1] = d.y; whh1[4*k+2] = d.z; whh1[4*k+3] = d.w;
        }
    }
    const float bias0 = bih0[tid] + bhh0[tid];
    const float bias1 = bih1[tid] + bhh1[tid];

    if (tid < 32) { h0A[tid] = 0.0f; h1A[tid] = 0.0f; h0B[tid] = 0.0f; h1B[tid] = 0.0f; }
    __syncthreads();

    float cA0 = 0.0f, cA1 = 0.0f, cB0 = 0.0f, cB1 = 0.0f;
    const float4* XA = reinterpret_cast<const float4*>(x + (size_t)bA * (TT * DD));
    const float4* XB = reinterpret_cast<const float4*>(x + (size_t)bB * (TT * DD));
    const float4* H0Ap = reinterpret_cast<const float4*>(h0A);
    const float4* H1Ap = reinterpret_cast<const float4*>(h1A);
    const float4* H0Bp = reinterpret_cast<const float4*>(h0B);
    const float4* H1Bp = reinterpret_cast<const float4*>(h1B);

    // ================= prologue: layer-0 gates for step 0 (h0 == 0) =================
    {
        float4 xa = XA[0], xb = XB[0];
        float pA = fmaf(xa.x, wih0[0], bias0);
        pA = fmaf(xa.y, wih0[1], pA);
        pA = fmaf(xa.z, wih0[2], pA);
        pA = fmaf(xa.w, wih0[3], pA);
        float pB = fmaf(xb.x, wih0[0], bias0);
        pB = fmaf(xb.y, wih0[1], pB);
        pB = fmaf(xb.z, wih0[2], pB);
        pB = fmaf(xb.w, wih0[3], pB);
        gA0[tid] = (gate == 2) ? ftanh(pA) : fsig(pA);
        gB0[tid] = (gate == 2) ? ftanh(pB) : fsig(pB);
    }
    __syncthreads();
    {   // redundant value-identical update in every warp (no 2nd barrier needed)
        float gi = gA0[lane], gf = gA0[32 + lane], gg = gA0[64 + lane], go = gA0[96 + lane];
        cA0 = fmaf(gf, cA0, gi * gg);
        h0A[lane] = go * ftanh(cA0);
        gi = gB0[lane]; gf = gB0[32 + lane]; gg = gB0[64 + lane]; go = gB0[96 + lane];
        cB0 = fmaf(gf, cB0, gi * gg);
        h0B[lane] = go * ftanh(cB0);
    }
    __syncwarp();

    float4 xvA = XA[1], xvB = XB[1];   // x for step 1

    // ===== main loop: ONE barrier per step; L1(t) and L0(t+1), both batches =====
    for (int t = 0; t < TT - 1; ++t) {
        const int tn = (t + 2 < TT) ? (t + 2) : (TT - 1);
        float4 xnA = XA[tn], xnB = XB[tn];      // prefetch

        // L0(t+1) accumulators (batch A / B)
        float sA0 = fmaf(xvA.x, wih0[0], bias0);
        float sA1 = xvA.y * wih0[1];
        float sA2 = xvA.z * wih0[2];
        float sA3 = xvA.w * wih0[3];
        float sB0 = fmaf(xvB.x, wih0[0], bias0);
        float sB1 = xvB.y * wih0[1];
        float sB2 = xvB.z * wih0[2];
        float sB3 = xvB.w * wih0[3];
        // L1(t) accumulators
        float uA0 = bias1, uA1 = 0.0f, uA2 = 0.0f, uA3 = 0.0f;
        float uB0 = bias1, uB1 = 0.0f, uB2 = 0.0f, uB3 = 0.0f;
        #pragma unroll
        for (int k = 0; k < 8; ++k) {
            float4 aA = H0Ap[k];                 // h0A(t): feeds 3 dots
            float4 hA = H1Ap[k];                 // h1A(t-1)
            float4 aB = H0Bp[k];
            float4 hB = H1Bp[k];
            uA0 = fmaf(aA.x, wih1[4*k+0], uA0);
            uA1 = fmaf(aA.y, wih1[4*k+1], uA1);
            uA2 = fmaf(aA.z, wih1[4*k+2], uA2);
            uA3 = fmaf(aA.w, wih1[4*k+3], uA3);
            uB0 = fmaf(aB.x, wih1[4*k+0], uB0);
            uB1 = fmaf(aB.y, wih1[4*k+1], uB1);
            uB2 = fmaf(aB.z, wih1[4*k+2], uB2);
            uB3 = fmaf(aB.w, wih1[4*k+3], uB3);
            uA0 = fmaf(hA.x, whh1[4*k+0], uA0);
            uA1 = fmaf(hA.y, whh1[4*k+1], uA1);
            uA2 = fmaf(hA.z, whh1[4*k+2], uA2);
            uA3 = fmaf(hA.w, whh1[4*k+3], uA3);
            uB0 = fmaf(hB.x, whh1[4*k+0], uB0);
            uB1 = fmaf(hB.y, whh1[4*k+1], uB1);
            uB2 = fmaf(hB.z, whh1[4*k+2], uB2);
            uB3 = fmaf(hB.w, whh1[4*k+3], uB3);
            sA0 = fmaf(aA.x, whh0[4*k+0], sA0);
            sA1 = fmaf(aA.y, whh0[4*k+1], sA1);
            sA2 = fmaf(aA.z, whh0[4*k+2], sA2);
            sA3 = fmaf(aA.w, whh0[4*k+3], sA3);
            sB0 = fmaf(aB.x, whh0[4*k+0], sB0);
            sB1 = fmaf(aB.y, whh0[4*k+1], sB1);
            sB2 = fmaf(aB.z, whh0[4*k+2], sB2);
            sB3 = fmaf(aB.w, whh0[4*k+3], sB3);
        }
        float preA1 = (uA0 + uA1) + (uA2 + uA3);
        float preB1 = (uB0 + uB1) + (uB2 + uB3);
        float preA0 = (sA0 + sA1) + (sA2 + sA3);
        float preB0 = (sB0 + sB1) + (sB2 + sB3);

        if (gate == 2) {
            gA1[tid] = ftanh(preA1);
            gB1[tid] = ftanh(preB1);
            gA0[tid] = ftanh(preA0);
            gB0[tid] = ftanh(preB0);
        } else {
            gA1[tid] = fsig(preA1);
            gB1[tid] = fsig(preB1);
            gA0[tid] = fsig(preA0);
            gB0[tid] = fsig(preB0);
        }
        __syncthreads();                      // the ONLY barrier per step

        {   // layer-1 update (step t), batches A and B
            float gi = gA1[lane], gf = gA1[32 + lane], gg = gA1[64 + lane], go = gA1[96 + lane];
            cA1 = fmaf(gf, cA1, gi * gg);
            h1A[lane] = go * ftanh(cA1);
            gi = gB1[lane]; gf = gB1[32 + lane]; gg = gB1[64 + lane]; go = gB1[96 + lane];
            cB1 = fmaf(gf, cB1, gi * gg);
            h1B[lane] = go * ftanh(cB1);
        }
        {   // layer-0 update (step t+1), batches A and B
            float gi = gA0[lane], gf = gA0[32 + lane], gg = gA0[64 + lane], go = gA0[96 + lane];
            cA0 = fmaf(gf, cA0, gi * gg);
            h0A[lane] = go * ftanh(cA0);
            gi = gB0[lane]; gf = gB0[32 + lane]; gg = gB0[64 + lane]; go = gB0[96 + lane];
            cB0 = fmaf(gf, cB0, gi * gg);
            h0B[lane] = go * ftanh(cB0);
        }
        __syncwarp();

        xvA = xnA; xvB = xnB;
    }

    // ================= epilogue: L1(TT-1), both batches =================
    {
        float uA0 = bias1, uA1 = 0.0f, uA2 = 0.0f, uA3 = 0.0f;
        float uB0 = bias1, uB1 = 0.0f, uB2 = 0.0f, uB3 = 0.0f;
        #pragma unroll
        for (int k = 0; k < 8; ++k) {
            float4 aA = H0Ap[k];
            float4 hA = H1Ap[k];
            float4 aB = H0Bp[k];
            float4 hB = H1Bp[k];
            uA0 = fmaf(aA.x, wih1[4*k+0], uA0);
            uA1 = fmaf(aA.y, wih1[4*k+1], uA1);
            uA2 = fmaf(aA.z, wih1[4*k+2], uA2);
            uA3 = fmaf(aA.w, wih1[4*k+3], uA3);
            uB0 = fmaf(aB.x, wih1[4*k+0], uB0);
            uB1 = fmaf(aB.y, wih1[4*k+1], uB1);
            uB2 = fmaf(aB.z, wih1[4*k+2], uB2);
            uB3 = fmaf(aB.w, wih1[4*k+3], uB3);
            uA0 = fmaf(hA.x, whh1[4*k+0], uA0);
            uA1 = fmaf(hA.y, whh1[4*k+1], uA1);
            uA2 = fmaf(hA.z, whh1[4*k+2], uA2);
            uA3 = fmaf(hA.w, whh1[4*k+3], uA3);
            uB0 = fmaf(hB.x, whh1[4*k+0], uB0);
            uB1 = fmaf(hB.y, whh1[4*k+1], uB1);
            uB2 = fmaf(hB.z, whh1[4*k+2], uB2);
            uB3 = fmaf(hB.w, whh1[4*k+3], uB3);
        }
        float preA1 = (uA0 + uA1) + (uA2 + uA3);
        float preB1 = (uB0 + uB1) + (uB2 + uB3);
        gA1[tid] = (gate == 2) ? ftanh(preA1) : fsig(preA1);
        gB1[tid] = (gate == 2) ? ftanh(preB1) : fsig(preB1);
    }
    __syncthreads();

    // -------- heads (warp 0 computes both batches; it holds cA1/cB1 per lane) -----
    if (tid < 32) {
        float gi = gA1[lane], gf = gA1[32 + lane], gg = gA1[64 + lane], go = gA1[96 + lane];
        cA1 = fmaf(gf, cA1, gi * gg);
        float hAf = go * ftanh(cA1);
        gi = gB1[lane]; gf = gB1[32 + lane]; gg = gB1[64 + lane]; go = gB1[96 + lane];
        cB1 = fmaf(gf, cB1, gi * gg);
        float hBf = go * ftanh(cB1);

        float w = Wout[lane];
        float vA = hAf * w;
        float vB = hBf * w;
        #pragma unroll
        for (int o = 16; o > 0; o >>= 1) {
            vA += __shfl_down_sync(0xffffffffu, vA, o);
            vB += __shfl_down_sync(0xffffffffu, vB, o);
        }
        if (lane == 0) {
            float bo = bout[0];
            out[bA] = vA + bo;
            out[bB] = vB + bo;
        }
    }
}

extern "C" void kernel_launch(void* const* d_in, const int* in_sizes, int n_in,
                              void* d_out, int out_size)
{
    const float* x    = (const float*)d_in[0];
    const float* Wih0 = (const float*)d_in[1];
    const float* Whh0 = (const float*)d_in[2];
    const float* bih0 = (const float*)d_in[3];
    const float* bhh0 = (const float*)d_in[4];
    const float* Wih1 = (const float*)d_in[5];
    const float* Whh1 = (const float*)d_in[6];
    const float* bih1 = (const float*)d_in[7];
    const float* bhh1 = (const float*)d_in[8];
    const float* Wout = (const float*)d_in[9];
    const float* bout = (const float*)d_in[10];

    const int B = out_size;     // 4096
    lstm2_kernel<<<B / 2, 128>>>(x, Wih0, Whh0, bih0, bhh0,
                                 Wih1, Whh1, bih1, bhh1,
                                 Wout, bout, (float*)d_out);
}

// round 6
// speedup vs baseline: 1.5400x; 1.0392x over previous
#include <cuda_runtime.h>

// x [B=4096, T=512, D=4], H=32, 2 stacked LSTM layers, gate rows i,f,g,o (0..127),
// head: out[b] = h2[T-1] . W_out + b_out.
// ONE block = TWO batches (A,B); shared weight registers; single barrier/step;
// MUFU.TANH activations; dot products packed 2-wide via fma.rn.f32x2.
#define TT 512
#define DD 4

typedef unsigned long long ull;

// ---- packed f32x2 helpers (sm_103a FFMA2 path, PTX-only) ----
__device__ __forceinline__ ull ffma2(ull a, ull b, ull c) {
    ull d;
    asm("fma.rn.f32x2 %0, %1, %2, %3;" : "=l"(d) : "l"(a), "l"(b), "l"(c));
    return d;
}
__device__ __forceinline__ ull fadd2(ull a, ull b) {
    ull d;
    asm("add.rn.f32x2 %0, %1, %2;" : "=l"(d) : "l"(a), "l"(b));
    return d;
}
__device__ __forceinline__ ull fpack(float lo, float hi) {
    ull d;
    asm("mov.b64 %0, {%1, %2};" : "=l"(d) : "f"(lo), "f"(hi));
    return d;
}
__device__ __forceinline__ float funpack_sum(ull p) {   // lo + hi
    float lo, hi;
    asm("mov.b64 {%0, %1}, %2;" : "=f"(lo), "=f"(hi) : "l"(p));
    return lo + hi;
}

__device__ __forceinline__ float tanh_hw(float x) {
    float y;
    asm("tanh.approx.f32 %0, %1;" : "=f"(y) : "f"(x));
    return y;
}
__device__ __forceinline__ float fsig(float x) {
    // sigmoid(x) = 0.5*tanh(0.5x) + 0.5
    return fmaf(0.5f, tanh_hw(0.5f * x), 0.5f);
}
__device__ __forceinline__ float ftanh(float x) { return tanh_hw(x); }

__global__ __launch_bounds__(128, 3)
void lstm2_kernel(const float* __restrict__ x,
                  const float* __restrict__ Wih0, const float* __restrict__ Whh0,
                  const float* __restrict__ bih0, const float* __restrict__ bhh0,
                  const float* __restrict__ Wih1, const float* __restrict__ Whh1,
                  const float* __restrict__ bih1, const float* __restrict__ bhh1,
                  const float* __restrict__ Wout, const float* __restrict__ bout,
                  float* __restrict__ out)
{
    const int bA   = blockIdx.x * 2;       // batch A
    const int bB   = bA + 1;               // batch B
    const int tid  = threadIdx.x;          // gate-row index: warps = i,f,g,o
    const int gate = tid >> 5;             // activation choice is warp-uniform
    const int lane = tid & 31;             // hidden unit

    __shared__ __align__(16) float h0A[32], h1A[32], h0B[32], h1B[32];
    __shared__ float gA0[128], gA1[128], gB0[128], gB1[128];

    // ---- weights resident as f32x2 register pairs, shared by both streams ----
    ull wih0p[2], whh0p[16], wih1p[16], whh1p[16];
    {
        const ulonglong2* r;
        r = reinterpret_cast<const ulonglong2*>(Wih0 + tid * 4);
        { ulonglong2 v = r[0]; wih0p[0] = v.x; wih0p[1] = v.y; }
        r = reinterpret_cast<const ulonglong2*>(Whh0 + tid * 32);
        #pragma unroll
        for (int k = 0; k < 8; ++k) { ulonglong2 v = r[k]; whh0p[2*k] = v.x; whh0p[2*k+1] = v.y; }
        r = reinterpret_cast<const ulonglong2*>(Wih1 + tid * 32);
        #pragma unroll
        for (int k = 0; k < 8; ++k) { ulonglong2 v = r[k]; wih1p[2*k] = v.x; wih1p[2*k+1] = v.y; }
        r = reinterpret_cast<const ulonglong2*>(Whh1 + tid * 32);
        #pragma unroll
        for (int k = 0; k < 8; ++k) { ulonglong2 v = r[k]; whh1p[2*k] = v.x; whh1p[2*k+1] = v.y; }
    }
    const float bias0 = bih0[tid] + bhh0[tid];
    const float bias1 = bih1[tid] + bhh1[tid];
    const ull bias0p = fpack(bias0, 0.0f);
    const ull bias1p = fpack(bias1, 0.0f);
    const ull ZP = 0ull;

    if (tid < 32) { h0A[tid] = 0.0f; h1A[tid] = 0.0f; h0B[tid] = 0.0f; h1B[tid] = 0.0f; }
    __syncthreads();

    float cA0 = 0.0f, cA1 = 0.0f, cB0 = 0.0f, cB1 = 0.0f;
    const ulonglong2* XA = reinterpret_cast<const ulonglong2*>(x + (size_t)bA * (TT * DD));
    const ulonglong2* XB = reinterpret_cast<const ulonglong2*>(x + (size_t)bB * (TT * DD));
    const ulonglong2* H0Ap = reinterpret_cast<const ulonglong2*>(h0A);
    const ulonglong2* H1Ap = reinterpret_cast<const ulonglong2*>(h1A);
    const ulonglong2* H0Bp = reinterpret_cast<const ulonglong2*>(h0B);
    const ulonglong2* H1Bp = reinterpret_cast<const ulonglong2*>(h1B);

    // ================= prologue: layer-0 gates for step 0 (h0 == 0) =================
    {
        ulonglong2 xa = XA[0], xb = XB[0];
        float pA = funpack_sum(fadd2(ffma2(xa.x, wih0p[0], bias0p),
                                     ffma2(xa.y, wih0p[1], ZP)));
        float pB = funpack_sum(fadd2(ffma2(xb.x, wih0p[0], bias0p),
                                     ffma2(xb.y, wih0p[1], ZP)));
        gA0[tid] = (gate == 2) ? ftanh(pA) : fsig(pA);
        gB0[tid] = (gate == 2) ? ftanh(pB) : fsig(pB);
    }
    __syncthreads();
    {   // redundant value-identical update in every warp (no 2nd barrier needed)
        float gi = gA0[lane], gf = gA0[32 + lane], gg = gA0[64 + lane], go = gA0[96 + lane];
        cA0 = fmaf(gf, cA0, gi * gg);
        h0A[lane] = go * ftanh(cA0);
        gi = gB0[lane]; gf = gB0[32 + lane]; gg = gB0[64 + lane]; go = gB0[96 + lane];
        cB0 = fmaf(gf, cB0, gi * gg);
        h0B[lane] = go * ftanh(cB0);
    }
    __syncwarp();

    ulonglong2 xvA = XA[1], xvB = XB[1];   // x for step 1

    // ===== main loop: ONE barrier per step; L1(t) and L0(t+1), both batches =====
    for (int t = 0; t < TT - 1; ++t) {
        const int tn = (t + 2 < TT) ? (t + 2) : (TT - 1);
        ulonglong2 xnA = XA[tn], xnB = XB[tn];      // prefetch

        // L0(t+1) packed accumulators (batch A / B)
        ull sA0 = ffma2(xvA.x, wih0p[0], bias0p);
        ull sA1 = ffma2(xvA.y, wih0p[1], ZP);
        ull sB0 = ffma2(xvB.x, wih0p[0], bias0p);
        ull sB1 = ffma2(xvB.y, wih0p[1], ZP);
        // L1(t) packed accumulators
        ull uA0 = bias1p, uA1 = ZP, uA2 = ZP, uA3 = ZP;
        ull uB0 = bias1p, uB1 = ZP, uB2 = ZP, uB3 = ZP;
        #pragma unroll
        for (int k = 0; k < 8; ++k) {
            ulonglong2 aA = H0Ap[k];                 // h0A(t): feeds 3 dots
            ulonglong2 hA = H1Ap[k];                 // h1A(t-1)
            ulonglong2 aB = H0Bp[k];
            ulonglong2 hB = H1Bp[k];
            uA0 = ffma2(aA.x, wih1p[2*k],   uA0);
            uA1 = ffma2(aA.y, wih1p[2*k+1], uA1);
            uB0 = ffma2(aB.x, wih1p[2*k],   uB0);
            uB1 = ffma2(aB.y, wih1p[2*k+1], uB1);
            uA2 = ffma2(hA.x, whh1p[2*k],   uA2);
            uA3 = ffma2(hA.y, whh1p[2*k+1], uA3);
            uB2 = ffma2(hB.x, whh1p[2*k],   uB2);
            uB3 = ffma2(hB.y, whh1p[2*k+1], uB3);
            sA0 = ffma2(aA.x, whh0p[2*k],   sA0);
            sA1 = ffma2(aA.y, whh0p[2*k+1], sA1);
            sB0 = ffma2(aB.x, whh0p[2*k],   sB0);
            sB1 = ffma2(aB.y, whh0p[2*k+1], sB1);
        }
        float preA1 = funpack_sum(fadd2(fadd2(uA0, uA1), fadd2(uA2, uA3)));
        float preB1 = funpack_sum(fadd2(fadd2(uB0, uB1), fadd2(uB2, uB3)));
        float preA0 = funpack_sum(fadd2(sA0, sA1));
        float preB0 = funpack_sum(fadd2(sB0, sB1));

        if (gate == 2) {
            gA1[tid] = ftanh(preA1);
            gB1[tid] = ftanh(preB1);
            gA0[tid] = ftanh(preA0);
            gB0[tid] = ftanh(preB0);
        } else {
            gA1[tid] = fsig(preA1);
            gB1[tid] = fsig(preB1);
            gA0[tid] = fsig(preA0);
            gB0[tid] = fsig(preB0);
        }
        __syncthreads();                      // the ONLY barrier per step

        {   // layer-1 update (step t), batches A and B
            float gi = gA1[lane], gf = gA1[32 + lane], gg = gA1[64 + lane], go = gA1[96 + lane];
            cA1 = fmaf(gf, cA1, gi * gg);
            h1A[lane] = go * ftanh(cA1);
            gi = gB1[lane]; gf = gB1[32 + lane]; gg = gB1[64 + lane]; go = gB1[96 + lane];
            cB1 = fmaf(gf, cB1, gi * gg);
            h1B[lane] = go * ftanh(cB1);
        }
        {   // layer-0 update (step t+1), batches A and B
            float gi = gA0[lane], gf = gA0[32 + lane], gg = gA0[64 + lane], go = gA0[96 + lane];
            cA0 = fmaf(gf, cA0, gi * gg);
            h0A[lane] = go * ftanh(cA0);
            gi = gB0[lane]; gf = gB0[32 + lane]; gg = gB0[64 + lane]; go = gB0[96 + lane];
            cB0 = fmaf(gf, cB0, gi * gg);
            h0B[lane] = go * ftanh(cB0);
        }
        __syncwarp();

        xvA = xnA; xvB = xnB;
    }

    // ================= epilogue: L1(TT-1), both batches =================
    {
        ull uA0 = bias1p, uA1 = ZP, uA2 = ZP, uA3 = ZP;
        ull uB0 = bias1p, uB1 = ZP, uB2 = ZP, uB3 = ZP;
        #pragma unroll
        for (int k = 0; k < 8; ++k) {
            ulonglong2 aA = H0Ap[k];
            ulonglong2 hA = H1Ap[k];
            ulonglong2 aB = H0Bp[k];
            ulonglong2 hB = H1Bp[k];
            uA0 = ffma2(aA.x, wih1p[2*k],   uA0);
            uA1 = ffma2(aA.y, wih1p[2*k+1], uA1);
            uB0 = ffma2(aB.x, wih1p[2*k],   uB0);
            uB1 = ffma2(aB.y, wih1p[2*k+1], uB1);
            uA2 = ffma2(hA.x, whh1p[2*k],   uA2);
            uA3 = ffma2(hA.y, whh1p[2*k+1], uA3);
            uB2 = ffma2(hB.x, whh1p[2*k],   uB2);
            uB3 = ffma2(hB.y, whh1p[2*k+1], uB3);
        }
        float preA1 = funpack_sum(fadd2(fadd2(uA0, uA1), fadd2(uA2, uA3)));
        float preB1 = funpack_sum(fadd2(fadd2(uB0, uB1), fadd2(uB2, uB3)));
        gA1[tid] = (gate == 2) ? ftanh(preA1) : fsig(preA1);
        gB1[tid] = (gate == 2) ? ftanh(preB1) : fsig(preB1);
    }
    __syncthreads();

    // -------- heads (warp 0 computes both batches; it holds cA1/cB1 per lane) -----
    if (tid < 32) {
        float gi = gA1[lane], gf = gA1[32 + lane], gg = gA1[64 + lane], go = gA1[96 + lane];
        cA1 = fmaf(gf, cA1, gi * gg);
        float hAf = go * ftanh(cA1);
        gi = gB1[lane]; gf = gB1[32 + lane]; gg = gB1[64 + lane]; go = gB1[96 + lane];
        cB1 = fmaf(gf, cB1, gi * gg);
        float hBf = go * ftanh(cB1);

        float w = Wout[lane];
        float vA = hAf * w;
        float vB = hBf * w;
        #pragma unroll
        for (int o = 16; o > 0; o >>= 1) {
            vA += __shfl_down_sync(0xffffffffu, vA, o);
            vB += __shfl_down_sync(0xffffffffu, vB, o);
        }
        if (lane == 0) {
            float bo = bout[0];
            out[bA] = vA + bo;
            out[bB] = vB + bo;
        }
    }
}

extern "C" void kernel_launch(void* const* d_in, const int* in_sizes, int n_in,
                              void* d_out, int out_size)
{
    const float* x    = (const float*)d_in[0];
    const float* Wih0 = (const float*)d_in[1];
    const float* Whh0 = (const float*)d_in[2];
    const float* bih0 = (const float*)d_in[3];
    const float* bhh0 = (const float*)d_in[4];
    const float* Wih1 = (const float*)d_in[5];
    const float* Whh1 = (const float*)d_in[6];
    const float* bih1 = (const float*)d_in[7];
    const float* bhh1 = (const float*)d_in[8];
    const float* Wout = (const float*)d_in[9];
    const float* bout = (const float*)d_in[10];

    const int B = out_size;     // 4096
    lstm2_kernel<<<B / 2, 128>>>(x, Wih0, Whh0, bih0, bhh0,
                                 Wih1, Whh1, bih1, bhh1,
                                 Wout, bout, (float*)d_out);
}

// round 7
// speedup vs baseline: 1.8031x; 1.1709x over previous
#include <cuda_runtime.h>

// x [B=4096, T=512, D=4], H=32, 2 stacked LSTM layers, gate rows i,f,g,o (0..127),
// head: out[b] = h2[T-1] . W_out + b_out.
// ONE block = TWO batches (A,B); weights in registers; FFMA2 dots; MUFU.TANH.
// This round: c/h updates PARTITIONED across the 128 threads (1 task each:
// warp0=(L1,A) warp1=(L1,B) warp2=(L0,A) warp3=(L0,B), lane=unit) with a
// second barrier, replacing the redundant all-warp updates (halves LSU bytes).
#define TT 512
#define DD 4

typedef unsigned long long ull;

__device__ __forceinline__ ull ffma2(ull a, ull b, ull c) {
    ull d;
    asm("fma.rn.f32x2 %0, %1, %2, %3;" : "=l"(d) : "l"(a), "l"(b), "l"(c));
    return d;
}
__device__ __forceinline__ ull fadd2(ull a, ull b) {
    ull d;
    asm("add.rn.f32x2 %0, %1, %2;" : "=l"(d) : "l"(a), "l"(b));
    return d;
}
__device__ __forceinline__ ull fpack(float lo, float hi) {
    ull d;
    asm("mov.b64 %0, {%1, %2};" : "=l"(d) : "f"(lo), "f"(hi));
    return d;
}
__device__ __forceinline__ float funpack_sum(ull p) {
    float lo, hi;
    asm("mov.b64 {%0, %1}, %2;" : "=f"(lo), "=f"(hi) : "l"(p));
    return lo + hi;
}

__device__ __forceinline__ float tanh_hw(float x) {
    float y;
    asm("tanh.approx.f32 %0, %1;" : "=f"(y) : "f"(x));
    return y;
}
__device__ __forceinline__ float fsig(float x) {
    return fmaf(0.5f, tanh_hw(0.5f * x), 0.5f);   // sigmoid via MUFU.TANH
}
__device__ __forceinline__ float ftanh(float x) { return tanh_hw(x); }

__global__ __launch_bounds__(128, 3)
void lstm2_kernel(const float* __restrict__ x,
                  const float* __restrict__ Wih0, const float* __restrict__ Whh0,
                  const float* __restrict__ bih0, const float* __restrict__ bhh0,
                  const float* __restrict__ Wih1, const float* __restrict__ Whh1,
                  const float* __restrict__ bih1, const float* __restrict__ bhh1,
                  const float* __restrict__ Wout, const float* __restrict__ bout,
                  float* __restrict__ out)
{
    const int bA   = blockIdx.x * 2;
    const int bB   = bA + 1;
    const int tid  = threadIdx.x;          // gate-row index for the dots
    const int gate = tid >> 5;             // warp = gate (i,f,g,o) AND update-task id
    const int lane = tid & 31;             // hidden unit

    __shared__ __align__(16) float h0A[32], h1A[32], h0B[32], h1B[32];
    __shared__ float gA0[128], gA1[128], gB0[128], gB1[128];

    // ---- weights resident as f32x2 register pairs, shared by both streams ----
    ull wih0p[2], whh0p[16], wih1p[16], whh1p[16];
    {
        const ulonglong2* r;
        r = reinterpret_cast<const ulonglong2*>(Wih0 + tid * 4);
        { ulonglong2 v = r[0]; wih0p[0] = v.x; wih0p[1] = v.y; }
        r = reinterpret_cast<const ulonglong2*>(Whh0 + tid * 32);
        #pragma unroll
        for (int k = 0; k < 8; ++k) { ulonglong2 v = r[k]; whh0p[2*k] = v.x; whh0p[2*k+1] = v.y; }
        r = reinterpret_cast<const ulonglong2*>(Wih1 + tid * 32);
        #pragma unroll
        for (int k = 0; k < 8; ++k) { ulonglong2 v = r[k]; wih1p[2*k] = v.x; wih1p[2*k+1] = v.y; }
        r = reinterpret_cast<const ulonglong2*>(Whh1 + tid * 32);
        #pragma unroll
        for (int k = 0; k < 8; ++k) { ulonglong2 v = r[k]; whh1p[2*k] = v.x; whh1p[2*k+1] = v.y; }
    }
    const ull bias0p = fpack(bih0[tid] + bhh0[tid], 0.0f);
    const ull bias1p = fpack(bih1[tid] + bhh1[tid], 0.0f);
    const ull ZP = 0ull;

    // ---- this thread's single update task: (layer, batch) by warp, unit = lane ----
    const float* gsrc = (gate == 0) ? gA1 : (gate == 1) ? gB1 : (gate == 2) ? gA0 : gB0;
    float*       hdst = (gate == 0) ? h1A : (gate == 1) ? h1B : (gate == 2) ? h0A : h0B;
    float cst = 0.0f;                      // the task's cell state

    if (tid < 32) { h0A[tid] = 0.0f; h1A[tid] = 0.0f; h0B[tid] = 0.0f; h1B[tid] = 0.0f; }
    __syncthreads();

    const ulonglong2* XA = reinterpret_cast<const ulonglong2*>(x + (size_t)bA * (TT * DD));
    const ulonglong2* XB = reinterpret_cast<const ulonglong2*>(x + (size_t)bB * (TT * DD));
    const ulonglong2* H0Ap = reinterpret_cast<const ulonglong2*>(h0A);
    const ulonglong2* H1Ap = reinterpret_cast<const ulonglong2*>(h1A);
    const ulonglong2* H0Bp = reinterpret_cast<const ulonglong2*>(h0B);
    const ulonglong2* H1Bp = reinterpret_cast<const ulonglong2*>(h1B);

    // ================= prologue: layer-0 gates for step 0 (h0 == 0) =================
    {
        ulonglong2 xa = XA[0], xb = XB[0];
        float pA = funpack_sum(fadd2(ffma2(xa.x, wih0p[0], bias0p),
                                     ffma2(xa.y, wih0p[1], ZP)));
        float pB = funpack_sum(fadd2(ffma2(xb.x, wih0p[0], bias0p),
                                     ffma2(xb.y, wih0p[1], ZP)));
        gA0[tid] = (gate == 2) ? ftanh(pA) : fsig(pA);
        gB0[tid] = (gate == 2) ? ftanh(pB) : fsig(pB);
    }
    __syncthreads();
    if (gate >= 2) {   // L0 tasks only at step 0
        float gi = gsrc[lane], gf = gsrc[32 + lane], gg = gsrc[64 + lane], go = gsrc[96 + lane];
        cst = fmaf(gf, cst, gi * gg);
        hdst[lane] = go * tanh_hw(cst);
    }
    __syncthreads();

    ulonglong2 xvA = XA[1], xvB = XB[1];

    // ===== main loop: dots -> BAR -> one update/thread -> BAR =====
    for (int t = 0; t < TT - 1; ++t) {
        const int tn = (t + 2 < TT) ? (t + 2) : (TT - 1);
        ulonglong2 xnA = XA[tn], xnB = XB[tn];      // prefetch

        // L0(t+1) packed accumulators (batch A / B)
        ull sA0 = ffma2(xvA.x, wih0p[0], bias0p);
        ull sA1 = ffma2(xvA.y, wih0p[1], ZP);
        ull sB0 = ffma2(xvB.x, wih0p[0], bias0p);
        ull sB1 = ffma2(xvB.y, wih0p[1], ZP);
        // L1(t) packed accumulators
        ull uA0 = bias1p, uA1 = ZP, uA2 = ZP, uA3 = ZP;
        ull uB0 = bias1p, uB1 = ZP, uB2 = ZP, uB3 = ZP;
        #pragma unroll
        for (int k = 0; k < 8; ++k) {
            ulonglong2 aA = H0Ap[k];
            ulonglong2 hA = H1Ap[k];
            ulonglong2 aB = H0Bp[k];
            ulonglong2 hB = H1Bp[k];
            uA0 = ffma2(aA.x, wih1p[2*k],   uA0);
            uA1 = ffma2(aA.y, wih1p[2*k+1], uA1);
            uB0 = ffma2(aB.x, wih1p[2*k],   uB0);
            uB1 = ffma2(aB.y, wih1p[2*k+1], uB1);
            uA2 = ffma2(hA.x, whh1p[2*k],   uA2);
            uA3 = ffma2(hA.y, whh1p[2*k+1], uA3);
            uB2 = ffma2(hB.x, whh1p[2*k],   uB2);
            uB3 = ffma2(hB.y, whh1p[2*k+1], uB3);
            sA0 = ffma2(aA.x, whh0p[2*k],   sA0);
            sA1 = ffma2(aA.y, whh0p[2*k+1], sA1);
            sB0 = ffma2(aB.x, whh0p[2*k],   sB0);
            sB1 = ffma2(aB.y, whh0p[2*k+1], sB1);
        }
        float preA1 = funpack_sum(fadd2(fadd2(uA0, uA1), fadd2(uA2, uA3)));
        float preB1 = funpack_sum(fadd2(fadd2(uB0, uB1), fadd2(uB2, uB3)));
        float preA0 = funpack_sum(fadd2(sA0, sA1));
        float preB0 = funpack_sum(fadd2(sB0, sB1));

        if (gate == 2) {
            gA1[tid] = ftanh(preA1);
            gB1[tid] = ftanh(preB1);
            gA0[tid] = ftanh(preA0);
            gB0[tid] = ftanh(preB0);
        } else {
            gA1[tid] = fsig(preA1);
            gB1[tid] = fsig(preB1);
            gA0[tid] = fsig(preA0);
            gB0[tid] = fsig(preB0);
        }
        __syncthreads();                      // BAR1: gates visible

        {   // ONE update task per thread (conflict-free LDS/STS)
            float gi = gsrc[lane], gf = gsrc[32 + lane], gg = gsrc[64 + lane], go = gsrc[96 + lane];
            cst = fmaf(gf, cst, gi * gg);
            hdst[lane] = go * tanh_hw(cst);
        }
        __syncthreads();                      // BAR2: h visible for next dots

        xvA = xnA; xvB = xnB;
    }

    // ================= epilogue: L1(TT-1), both batches =================
    {
        ull uA0 = bias1p, uA1 = ZP, uA2 = ZP, uA3 = ZP;
        ull uB0 = bias1p, uB1 = ZP, uB2 = ZP, uB3 = ZP;
        #pragma unroll
        for (int k = 0; k < 8; ++k) {
            ulonglong2 aA = H0Ap[k];
            ulonglong2 hA = H1Ap[k];
            ulonglong2 aB = H0Bp[k];
            ulonglong2 hB = H1Bp[k];
            uA0 = ffma2(aA.x, wih1p[2*k],   uA0);
            uA1 = ffma2(aA.y, wih1p[2*k+1], uA1);
            uB0 = ffma2(aB.x, wih1p[2*k],   uB0);
            uB1 = ffma2(aB.y, wih1p[2*k+1], uB1);
            uA2 = ffma2(hA.x, whh1p[2*k],   uA2);
            uA3 = ffma2(hA.y, whh1p[2*k+1], uA3);
            uB2 = ffma2(hB.x, whh1p[2*k],   uB2);
            uB3 = ffma2(hB.y, whh1p[2*k+1], uB3);
        }
        float preA1 = funpack_sum(fadd2(fadd2(uA0, uA1), fadd2(uA2, uA3)));
        float preB1 = funpack_sum(fadd2(fadd2(uB0, uB1), fadd2(uB2, uB3)));
        gA1[tid] = (gate == 2) ? ftanh(preA1) : fsig(preA1);
        gB1[tid] = (gate == 2) ? ftanh(preB1) : fsig(preB1);
    }
    __syncthreads();
    if (gate < 2) {   // final L1 updates
        float gi = gsrc[lane], gf = gsrc[32 + lane], gg = gsrc[64 + lane], go = gsrc[96 + lane];
        cst = fmaf(gf, cst, gi * gg);
        hdst[lane] = go * tanh_hw(cst);
    }
    __syncthreads();

    // -------- head: out = h1(final) . Wout + bout (warp 0, both batches) --------
    if (tid < 32) {
        float w = Wout[lane];
        float vA = h1A[lane] * w;
        float vB = h1B[lane] * w;
        #pragma unroll
        for (int o = 16; o > 0; o >>= 1) {
            vA += __shfl_down_sync(0xffffffffu, vA, o);
            vB += __shfl_down_sync(0xffffffffu, vB, o);
        }
        if (lane == 0) {
            float bo = bout[0];
            out[bA] = vA + bo;
            out[bB] = vB + bo;
        }
    }
}

extern "C" void kernel_launch(void* const* d_in, const int* in_sizes, int n_in,
                              void* d_out, int out_size)
{
    const float* x    = (const float*)d_in[0];
    const float* Wih0 = (const float*)d_in[1];
    const float* Whh0 = (const float*)d_in[2];
    const float* bih0 = (const float*)d_in[3];
    const float* bhh0 = (const float*)d_in[4];
    const float* Wih1 = (const float*)d_in[5];
    const float* Whh1 = (const float*)d_in[6];
    const float* bih1 = (const float*)d_in[7];
    const float* bhh1 = (const float*)d_in[8];
    const float* Wout = (const float*)d_in[9];
    const float* bout = (const float*)d_in[10];

    const int B = out_size;     // 4096
    lstm2_kernel<<<B / 2, 128>>>(x, Wih0, Whh0, bih0, bhh0,
                                 Wih1, Whh1, bih1, bhh1,
                                 Wout, bout, (float*)d_out);
}